// round 11
// baseline (speedup 1.0000x reference)
#include <cuda_runtime.h>
#include <cstdint>

// ROIRotate: B=2048 boxes, crop 8x64x32 bilinear samples from (8,128,128,32) fp32
// feature map. Output: crops [B,8,64,32] fp32 followed by padded_width [B] fp32.
//
// Two-kernel scheme (best known structure):
//   1) box_prep: per-box geometry (incl. division) -> __device__ scratch, writes pw.
//   2) roi_main: 4 v-values per thread (v = vp, vp+2, vp+4, vp+6), 8 c4-lanes
//      cover one full 128B pixel line per LDG.128, 16 independent gathers/thread.

#define HEIGHT_  8
#define MAXW_    64
#define C_       32
#define H_       128
#define W_       128
#define MAXB_    4096

__device__ float g_boxparams[MAXB_ * 8]; // x1,y1,box_w,box_h | inv_w,width,base_off(int),unused

__global__ void box_prep_kernel(const float* __restrict__ boxes,
                                const int* __restrict__ box_idx,
                                int B,
                                float* __restrict__ out_pw)
{
    const int b = blockIdx.x * blockDim.x + threadIdx.x;
    if (b >= B) return;

    const float* bx = boxes + b * 9;
    const float x1 = bx[0] * 0.25f;
    const float y1 = bx[1] * 0.25f;
    const float x2 = bx[2] * 0.25f;
    const float y4 = bx[7] * 0.25f;

    const float box_w = x2 - x1;
    const float box_h = y4 - y1;
    float width = (float)HEIGHT_ * box_w / fmaxf(box_h, 1e-6f);
    width = fminf(fmaxf(width, 1.0f), (float)MAXW_);

    out_pw[b] = (float)MAXW_ - width;

    const int base_off = box_idx[b] * (H_ * W_ * C_);

    float4* s = (float4*)(g_boxparams + b * 8);
    s[0] = make_float4(x1, y1, box_w, box_h);
    s[1] = make_float4(1.0f / width, width, __int_as_float(base_off), 0.0f);
}

__global__ void __launch_bounds__(256, 3)
roi_main_kernel(const float* __restrict__ fm,
                float* __restrict__ out_crops)
{
    // tid = b*1024 + vp*512 + u*8 + c4 ; thread handles v = vp, vp+2, vp+4, vp+6.
    const int tid = blockIdx.x * blockDim.x + threadIdx.x;
    const int c4 = tid & 7;
    const int u  = (tid >> 3) & 63;
    const int vp = (tid >> 9) & 1;
    const int b  = tid >> 10;

    const float4 p0 = ((const float4*)g_boxparams)[b * 2];      // x1,y1,box_w,box_h
    const float4 p1 = ((const float4*)g_boxparams)[b * 2 + 1];  // inv_w,width,base_off

    float4 acc[4];
#pragma unroll
    for (int k = 0; k < 4; k++) acc[k] = make_float4(0.f, 0.f, 0.f, 0.f);

    if ((float)u < p1.y) {
        // x geometry (shared by all 4 v values)
        const float tu = (float)u * p1.x;
        const float sx = p0.x + tu * p0.z;
        const float xf = floorf(sx);
        const float wx = sx - xf;
        const int x0i = min(max((int)xf, 0), W_ - 1);
        const int x1i = min(x0i + 1, W_ - 1);

        const float* base = fm + __float_as_int(p1.z) + (c4 << 2);

        float wyv[4];
        int y0v[4], y1v[4];
#pragma unroll
        for (int k = 0; k < 4; k++) {
            const int v = vp + 2 * k;
            const float tv = (float)v * (1.0f / (float)HEIGHT_);
            const float sy = p0.y + tv * p0.w;
            const float yf = floorf(sy);
            wyv[k] = sy - yf;
            const int y0 = min(max((int)yf, 0), H_ - 1);
            y0v[k] = y0;
            y1v[k] = min(y0 + 1, H_ - 1);
        }

        // 16 independent full-line-cooperative LDG.128
        float4 g00[4], g01[4], g10[4], g11[4];
#pragma unroll
        for (int k = 0; k < 4; k++) {
            g00[k] = *(const float4*)(base + (y0v[k] * W_ + x0i) * C_);
            g01[k] = *(const float4*)(base + (y0v[k] * W_ + x1i) * C_);
            g10[k] = *(const float4*)(base + (y1v[k] * W_ + x0i) * C_);
            g11[k] = *(const float4*)(base + (y1v[k] * W_ + x1i) * C_);
        }

#pragma unroll
        for (int k = 0; k < 4; k++) {
            const float wy = wyv[k];
            const float w00 = (1.f - wy) * (1.f - wx);
            const float w01 = (1.f - wy) * wx;
            const float w10 = wy * (1.f - wx);
            const float w11 = wy * wx;
            acc[k].x = w00 * g00[k].x + w01 * g01[k].x + w10 * g10[k].x + w11 * g11[k].x;
            acc[k].y = w00 * g00[k].y + w01 * g01[k].y + w10 * g10[k].y + w11 * g11[k].y;
            acc[k].z = w00 * g00[k].z + w01 * g01[k].z + w10 * g10[k].z + w11 * g11[k].z;
            acc[k].w = w00 * g00[k].w + w01 * g01[k].w + w10 * g10[k].w + w11 * g11[k].w;
        }
    }

    // out pixel (b, v, u): float4 index = ((b*8 + v)*64 + u)*8 + c4
    float4* o = (float4*)out_crops;
    const int pbase = ((b * 8 + vp) * 64 + u) * 8 + c4;
#pragma unroll
    for (int k = 0; k < 4; k++) {
        o[pbase + k * 2 * 64 * 8] = acc[k];
    }
}

extern "C" void kernel_launch(void* const* d_in, const int* in_sizes, int n_in,
                              void* d_out, int out_size)
{
    const float* fm    = (const float*)d_in[0];      // (8,128,128,32) f32
    const float* boxes = (const float*)d_in[1];      // (2048,9) f32
    const int*   bidx  = (const int*)d_in[2];        // (2048,) i32

    const int B = in_sizes[1] / 9;                   // 2048

    float* out_crops = (float*)d_out;
    float* out_pw    = (float*)d_out + (size_t)B * HEIGHT_ * MAXW_ * C_;

    box_prep_kernel<<<(B + 255) / 256, 256>>>(boxes, bidx, B, out_pw);

    const int total_threads = B * 2 * MAXW_ * (C_ / 4);  // 2,097,152
    const int block = 256;
    const int grid  = total_threads / block;             // 8192

    roi_main_kernel<<<grid, block>>>(fm, out_crops);
}

// round 12
// speedup vs baseline: 1.3225x; 1.3225x over previous
#include <cuda_runtime.h>
#include <cstdint>

// ROIRotate: B=2048 boxes, crop 8x64x32 bilinear samples from (8,128,128,32) fp32
// feature map. Output: crops [B,8,64,32] fp32 followed by padded_width [B] fp32.
//
// Two-kernel scheme (R5 structure, best known: kernel 27.5us):
//   1) box_prep: per-box geometry (incl. division) -> __device__ scratch, writes pw.
//   2) roi_main: 2 v-values per thread (v = vp, vp+4), 8 c4-lanes cover one full
//      128B pixel line per LDG.128, 8 independent gathers/thread, regs=32.
// R11 delta vs R5: output stores use st.global.cs (streaming, evict-first) so the
// 134MB write stream doesn't evict the 17MB L2-resident feature map.

#define HEIGHT_  8
#define MAXW_    64
#define C_       32
#define H_       128
#define W_       128
#define MAXB_    4096

__device__ float g_boxparams[MAXB_ * 8]; // x1,y1,box_w,box_h | inv_w,width,base_off(int),unused

__global__ void box_prep_kernel(const float* __restrict__ boxes,
                                const int* __restrict__ box_idx,
                                int B,
                                float* __restrict__ out_pw)
{
    const int b = blockIdx.x * blockDim.x + threadIdx.x;
    if (b >= B) return;

    const float* bx = boxes + b * 9;
    const float x1 = bx[0] * 0.25f;
    const float y1 = bx[1] * 0.25f;
    const float x2 = bx[2] * 0.25f;
    const float y4 = bx[7] * 0.25f;

    const float box_w = x2 - x1;
    const float box_h = y4 - y1;
    float width = (float)HEIGHT_ * box_w / fmaxf(box_h, 1e-6f);
    width = fminf(fmaxf(width, 1.0f), (float)MAXW_);

    out_pw[b] = (float)MAXW_ - width;

    const int base_off = box_idx[b] * (H_ * W_ * C_);

    float4* s = (float4*)(g_boxparams + b * 8);
    s[0] = make_float4(x1, y1, box_w, box_h);
    s[1] = make_float4(1.0f / width, width, __int_as_float(base_off), 0.0f);
}

__global__ void __launch_bounds__(256)
roi_main_kernel(const float* __restrict__ fm,
                float* __restrict__ out_crops)
{
    // tid = b*2048 + vp*512 + u*8 + c4 ; thread handles v=vp and v=vp+4.
    const int tid = blockIdx.x * blockDim.x + threadIdx.x;
    const int c4 = tid & 7;
    const int u  = (tid >> 3) & 63;
    const int vp = (tid >> 9) & 3;
    const int b  = tid >> 11;

    const float4 p0 = ((const float4*)g_boxparams)[b * 2];      // x1,y1,box_w,box_h
    const float4 p1 = ((const float4*)g_boxparams)[b * 2 + 1];  // inv_w,width,base_off

    float4 ra = make_float4(0.f, 0.f, 0.f, 0.f);
    float4 rb = make_float4(0.f, 0.f, 0.f, 0.f);

    if ((float)u < p1.y) {
        // x geometry (shared by both v values)
        const float tu = (float)u * p1.x;
        const float sx = p0.x + tu * p0.z;
        const float xf = floorf(sx);
        const float wx = sx - xf;
        const int x0i = min(max((int)xf, 0), W_ - 1);
        const int x1i = min(x0i + 1, W_ - 1);

        // y geometry for v = vp and v = vp+4
        const float tva = (float)vp       * (1.0f / (float)HEIGHT_);
        const float tvb = (float)(vp + 4) * (1.0f / (float)HEIGHT_);
        const float sya = p0.y + tva * p0.w;
        const float syb = p0.y + tvb * p0.w;
        const float yfa = floorf(sya);
        const float yfb = floorf(syb);
        const float wya = sya - yfa;
        const float wyb = syb - yfb;
        const int y0a = min(max((int)yfa, 0), H_ - 1);
        const int y1a = min(y0a + 1, H_ - 1);
        const int y0b = min(max((int)yfb, 0), H_ - 1);
        const int y1b = min(y0b + 1, H_ - 1);

        const float* base = fm + __float_as_int(p1.z) + (c4 << 2);

        // 8 independent full-line-cooperative LDG.128
        const float4 a00 = *(const float4*)(base + (y0a * W_ + x0i) * C_);
        const float4 a01 = *(const float4*)(base + (y0a * W_ + x1i) * C_);
        const float4 a10 = *(const float4*)(base + (y1a * W_ + x0i) * C_);
        const float4 a11 = *(const float4*)(base + (y1a * W_ + x1i) * C_);
        const float4 b00 = *(const float4*)(base + (y0b * W_ + x0i) * C_);
        const float4 b01 = *(const float4*)(base + (y0b * W_ + x1i) * C_);
        const float4 b10 = *(const float4*)(base + (y1b * W_ + x0i) * C_);
        const float4 b11 = *(const float4*)(base + (y1b * W_ + x1i) * C_);

        {
            const float w00 = (1.f - wya) * (1.f - wx);
            const float w01 = (1.f - wya) * wx;
            const float w10 = wya * (1.f - wx);
            const float w11 = wya * wx;
            ra.x = w00 * a00.x + w01 * a01.x + w10 * a10.x + w11 * a11.x;
            ra.y = w00 * a00.y + w01 * a01.y + w10 * a10.y + w11 * a11.y;
            ra.z = w00 * a00.z + w01 * a01.z + w10 * a10.z + w11 * a11.z;
            ra.w = w00 * a00.w + w01 * a01.w + w10 * a10.w + w11 * a11.w;
        }
        {
            const float w00 = (1.f - wyb) * (1.f - wx);
            const float w01 = (1.f - wyb) * wx;
            const float w10 = wyb * (1.f - wx);
            const float w11 = wyb * wx;
            rb.x = w00 * b00.x + w01 * b01.x + w10 * b10.x + w11 * b11.x;
            rb.y = w00 * b00.y + w01 * b01.y + w10 * b10.y + w11 * b11.y;
            rb.z = w00 * b00.z + w01 * b01.z + w10 * b10.z + w11 * b11.z;
            rb.w = w00 * b00.w + w01 * b01.w + w10 * b10.w + w11 * b11.w;
        }
    }

    // out pixel (b, v, u): float4 index = ((b*8 + v)*64 + u)*8 + c4
    // Streaming stores: output is write-once, never re-read -> evict-first in L2.
    float4* o = (float4*)out_crops;
    const int pa = ((b * 8 + vp)     * 64 + u) * 8 + c4;
    const int pb = ((b * 8 + vp + 4) * 64 + u) * 8 + c4;
    __stcs(o + pa, ra);
    __stcs(o + pb, rb);
}

extern "C" void kernel_launch(void* const* d_in, const int* in_sizes, int n_in,
                              void* d_out, int out_size)
{
    const float* fm    = (const float*)d_in[0];      // (8,128,128,32) f32
    const float* boxes = (const float*)d_in[1];      // (2048,9) f32
    const int*   bidx  = (const int*)d_in[2];        // (2048,) i32

    const int B = in_sizes[1] / 9;                   // 2048

    float* out_crops = (float*)d_out;
    float* out_pw    = (float*)d_out + (size_t)B * HEIGHT_ * MAXW_ * C_;

    box_prep_kernel<<<(B + 255) / 256, 256>>>(boxes, bidx, B, out_pw);

    const int total_threads = B * 4 * MAXW_ * (C_ / 4);  // 4,194,304
    const int block = 256;
    const int grid  = total_threads / block;             // 16384

    roi_main_kernel<<<grid, block>>>(fm, out_crops);
}